// round 16
// baseline (speedup 1.0000x reference)
#include <cuda_runtime.h>

typedef unsigned long long u64;

#define NCTA 128
#define NTHR 256
#define B_   32
#define S_   1024
#define IN_  128
#define H_   512
#define OUT_ 128

// ---------------- device scratch (static __device__ arrays: allowed) --------
__device__ unsigned g_cnt[4][32];                              // per-group barrier
__device__ __align__(128) float g_h[3][B_ * H_];               // state [l][b][k]
__device__ __align__(128) float g_rh[3][B_ * H_];              // r*h  [l][b][k]
__device__ __align__(128) float g_hist[(size_t)S_ * H_ * B_];  // [t][k][b] 64MB

// ---------------- SMEM layout (u64 units) -----------------------------------
// weights as k-pairs {w[k],w[k+1]}, permuted [row][kk][ks] so the 8 in-warp ks
// values are 16B apart (conflict-free LDS.128, 1 wavefront).
#define WXZ 0
#define WXR 4096
#define WXG 8192
#define WHZ 12288
#define WHR 16384
#define WHG 20480
#define W0Z 24576
#define W0R 25600
#define W0G 26624
#define SM64_TOTAL 27648
#define BIASF (SM64_TOTAL * 2)                 // float index of bias block
#define SMEM_BYTES (SM64_TOTAL * 8 + 96 * 4)   // 221,568 B

struct alignas(16) U2 { u64 a, b; };

__device__ __forceinline__ void fma2(u64& c, u64 a, u64 b) {
    asm("fma.rn.f32x2 %0, %1, %2, %0;" : "+l"(c) : "l"(a), "l"(b));
}
__device__ __forceinline__ void add2(u64& c, u64 a) {
    asm("add.rn.f32x2 %0, %0, %1;" : "+l"(c) : "l"(a));
}
__device__ __forceinline__ void pack2(const float4 v, u64& lo, u64& hi) {
    asm("mov.b64 %0, {%1, %2};" : "=l"(lo) : "f"(v.x), "f"(v.y));
    asm("mov.b64 %0, {%1, %2};" : "=l"(hi) : "f"(v.z), "f"(v.w));
}
__device__ __forceinline__ float foldu(u64 v) {
    float lo, hi;
    asm("mov.b64 {%0, %1}, %2;" : "=f"(lo), "=f"(hi) : "l"(v));
    return lo + hi;
}
// reduce over the 8 ks lanes (lane&7 groups)
__device__ __forceinline__ u64 red8(u64 v) {
    add2(v, __shfl_xor_sync(0xffffffffu, v, 1));
    add2(v, __shfl_xor_sync(0xffffffffu, v, 2));
    add2(v, __shfl_xor_sync(0xffffffffu, v, 4));
    return v;
}
__device__ __forceinline__ float sigf(float x) {
    return __fdividef(1.f, 1.f + __expf(-x));
}
__device__ __forceinline__ float tanhfast(float x) {
    return fmaf(2.f, __fdividef(1.f, 1.f + __expf(-2.f * x)), -1.f);
}

// 32-CTA batch-group barrier: release-arrive + acquire-poll
__device__ __forceinline__ void gbar(int bg, unsigned& target) {
    __syncthreads();
    if (threadIdx.x == 0) {
        target += 32;
        unsigned* c = &g_cnt[bg][0];
        asm volatile("red.release.gpu.global.add.u32 [%0], 1;" :: "l"(c) : "memory");
        unsigned v;
        do {
            asm volatile("ld.acquire.gpu.global.u32 %0, [%1];"
                         : "=r"(v) : "l"(c) : "memory");
        } while (v < target);
    }
    __syncthreads();
}

// ---------------- init: reset barriers, fill g_h from h0 --------------------
__global__ void init_kernel(const float* __restrict__ h0) {
    int idx = blockIdx.x * blockDim.x + threadIdx.x;
    if (idx < 128) ((unsigned*)g_cnt)[idx] = 0;
    if (idx < 3 * B_ * H_) {
        int l = idx >> 14;
        int rem = idx & 16383;
        int b = rem >> 9, k = rem & 511;
        g_h[l][b * H_ + k] = h0[b * (3 * H_) + l * H_ + k];
    }
}

// ---------------- persistent GRU kernel --------------------------------------
__global__ void __launch_bounds__(NTHR, 1) gru_persistent(
    const float* __restrict__ x,   const float* __restrict__ h0,
    const float* __restrict__ W0z, const float* __restrict__ b0z,
    const float* __restrict__ W0r, const float* __restrict__ b0r,
    const float* __restrict__ W0g, const float* __restrict__ b0g,
    const float* __restrict__ Wxz, const float* __restrict__ bxz,
    const float* __restrict__ Wxr, const float* __restrict__ bxr,
    const float* __restrict__ Wxg, const float* __restrict__ bxg,
    const float* __restrict__ Whz, const float* __restrict__ Whr,
    const float* __restrict__ Whg)
{
    extern __shared__ u64 sm64[];
    float* smf = (float*)sm64;
    const int tid = threadIdx.x;
    const int rowgrid = blockIdx.x >> 2, bg = blockIdx.x & 3;
    const int row_base = rowgrid * 16, b_base = bg * 8;

    // ---- stage weight slices (k-pair permuted layout) ----
    for (int e = tid; e < 16 * H_; e += NTHR) {
        int r = e >> 9, k = e & 511;
        int c = k >> 2, q = k & 3;
        int fidx = (((r * 16 + (c >> 3)) * 8) + (c & 7)) * 4 + q;
        int gi = (row_base + r) * H_ + k;
        smf[WXZ * 2 + fidx] = Wxz[gi];
        smf[WXR * 2 + fidx] = Wxr[gi];
        smf[WXG * 2 + fidx] = Wxg[gi];
        smf[WHZ * 2 + fidx] = Whz[gi];
        smf[WHR * 2 + fidx] = Whr[gi];
        smf[WHG * 2 + fidx] = Whg[gi];
    }
    for (int e = tid; e < 16 * IN_; e += NTHR) {
        int r = e >> 7, k = e & 127;
        int c = k >> 2, q = k & 3;
        int fidx = (((r * 4 + (c >> 3)) * 8) + (c & 7)) * 4 + q;
        int gi = (row_base + r) * IN_ + k;
        smf[W0Z * 2 + fidx] = W0z[gi];
        smf[W0R * 2 + fidx] = W0r[gi];
        smf[W0G * 2 + fidx] = W0g[gi];
    }
    if (tid < 16) {
        smf[BIASF + 0 * 16 + tid] = b0z[row_base + tid];
        smf[BIASF + 1 * 16 + tid] = b0r[row_base + tid];
        smf[BIASF + 2 * 16 + tid] = b0g[row_base + tid];
        smf[BIASF + 3 * 16 + tid] = bxz[row_base + tid];
        smf[BIASF + 4 * 16 + tid] = bxr[row_base + tid];
        smf[BIASF + 5 * 16 + tid] = bxg[row_base + tid];
    }
    __syncthreads();

    const int wr0  = (tid >> 5) * 2;        // warp's row pair (0..14)
    const int bgrp = (tid >> 3) & 3;
    const int b0a  = b_base + bgrp * 2;     // absolute batch for j=0
    const int ks   = tid & 7;
    const bool pub = (ks == 0);
    const int row_abs0 = row_base + wr0;

    float h_reg[3][2][2], zv[2][2], sg[2][2];
#pragma unroll
    for (int l = 0; l < 3; l++)
#pragma unroll
        for (int r = 0; r < 2; r++)
#pragma unroll
            for (int j = 0; j < 2; j++)
                h_reg[l][r][j] =
                    h0[(size_t)(b0a + j) * (3 * H_) + l * H_ + row_abs0 + r];

    unsigned target = 0;

    for (int t = 0; t < S_; t++) {
        for (int l = 0; l < 3; l++) {
            // ============ phase A: z/r full dots + xg input-side dot =========
            u64 az[2][2], ar[2][2], ag[2][2];
#pragma unroll
            for (int r = 0; r < 2; r++)
#pragma unroll
                for (int j = 0; j < 2; j++) {
                    az[r][j] = 0ull; ar[r][j] = 0ull; ag[r][j] = 0ull;
                }

            if (l == 0) {
                // --- input side: x (IN=128 -> 4 chunks/thread), gates z,r,g --
                const float4* xp0 =
                    (const float4*)(x + ((size_t)b0a * S_ + t) * IN_);
                const float4* xp1 = xp0 + (size_t)S_ * IN_ / 4;  // next batch
                float4 qx0[4], qx1[4];
#pragma unroll
                for (int kk = 0; kk < 4; kk++) {
                    qx0[kk] = __ldcg(xp0 + kk * 8 + ks);
                    qx1[kk] = __ldcg(xp1 + kk * 8 + ks);
                }
#pragma unroll
                for (int kk = 0; kk < 4; kk++) {
                    u64 xa0, xb0, xa1, xb1;
                    pack2(qx0[kk], xa0, xb0);
                    pack2(qx1[kk], xa1, xb1);
#pragma unroll
                    for (int r = 0; r < 2; r++) {
                        int wi = (((wr0 + r) * 4 + kk) * 8 + ks) * 2;
                        U2 w;
                        w = *(const U2*)&sm64[W0Z + wi];
                        fma2(az[r][0], xa0, w.a); fma2(az[r][0], xb0, w.b);
                        fma2(az[r][1], xa1, w.a); fma2(az[r][1], xb1, w.b);
                        w = *(const U2*)&sm64[W0R + wi];
                        fma2(ar[r][0], xa0, w.a); fma2(ar[r][0], xb0, w.b);
                        fma2(ar[r][1], xa1, w.a); fma2(ar[r][1], xb1, w.b);
                        w = *(const U2*)&sm64[W0G + wi];
                        fma2(ag[r][0], xa0, w.a); fma2(ag[r][0], xb0, w.b);
                        fma2(ag[r][1], xa1, w.a); fma2(ag[r][1], xb1, w.b);
                    }
                }
                // --- hidden side: h @ Whz/Whr ---
                const float4* hp0 = (const float4*)(g_h[0] + b0a * H_);
                const float4* hp1 = hp0 + H_ / 4;
                float4 qh0[2], qh1[2];
#pragma unroll
                for (int i = 0; i < 2; i++) {
                    qh0[i] = __ldcg(hp0 + i * 8 + ks);
                    qh1[i] = __ldcg(hp1 + i * 8 + ks);
                }
#pragma unroll
                for (int kk = 0; kk < 16; kk++) {
                    u64 ha0, hb0, ha1, hb1;
                    pack2(qh0[kk & 1], ha0, hb0);
                    pack2(qh1[kk & 1], ha1, hb1);
                    if (kk < 14) {
                        int c = (kk + 2) * 8 + ks;
                        qh0[kk & 1] = __ldcg(hp0 + c);
                        qh1[kk & 1] = __ldcg(hp1 + c);
                    }
#pragma unroll
                    for (int r = 0; r < 2; r++) {
                        int wi = (((wr0 + r) * 16 + kk) * 8 + ks) * 2;
                        U2 w;
                        w = *(const U2*)&sm64[WHZ + wi];
                        fma2(az[r][0], ha0, w.a); fma2(az[r][0], hb0, w.b);
                        fma2(az[r][1], ha1, w.a); fma2(az[r][1], hb1, w.b);
                        w = *(const U2*)&sm64[WHR + wi];
                        fma2(ar[r][0], ha0, w.a); fma2(ar[r][0], hb0, w.b);
                        fma2(ar[r][1], ha1, w.a); fma2(ar[r][1], hb1, w.b);
                    }
                }
            } else {
                const float4* xp0 = (const float4*)(g_h[l - 1] + b0a * H_);
                const float4* xp1 = xp0 + H_ / 4;
                const float4* hp0 = (const float4*)(g_h[l] + b0a * H_);
                const float4* hp1 = hp0 + H_ / 4;
                float4 qx0[2], qx1[2], qh0[2], qh1[2];
#pragma unroll
                for (int i = 0; i < 2; i++) {
                    qx0[i] = __ldcg(xp0 + i * 8 + ks);
                    qx1[i] = __ldcg(xp1 + i * 8 + ks);
                    qh0[i] = __ldcg(hp0 + i * 8 + ks);
                    qh1[i] = __ldcg(hp1 + i * 8 + ks);
                }
#pragma unroll
                for (int kk = 0; kk < 16; kk++) {
                    u64 xa0, xb0, xa1, xb1, ha0, hb0, ha1, hb1;
                    pack2(qx0[kk & 1], xa0, xb0);
                    pack2(qx1[kk & 1], xa1, xb1);
                    pack2(qh0[kk & 1], ha0, hb0);
                    pack2(qh1[kk & 1], ha1, hb1);
                    if (kk < 14) {
                        int c = (kk + 2) * 8 + ks;
                        qx0[kk & 1] = __ldcg(xp0 + c);
                        qx1[kk & 1] = __ldcg(xp1 + c);
                        qh0[kk & 1] = __ldcg(hp0 + c);
                        qh1[kk & 1] = __ldcg(hp1 + c);
                    }
#pragma unroll
                    for (int r = 0; r < 2; r++) {
                        int wi = (((wr0 + r) * 16 + kk) * 8 + ks) * 2;
                        U2 w;
                        w = *(const U2*)&sm64[WXZ + wi];
                        fma2(az[r][0], xa0, w.a); fma2(az[r][0], xb0, w.b);
                        fma2(az[r][1], xa1, w.a); fma2(az[r][1], xb1, w.b);
                        w = *(const U2*)&sm64[WXR + wi];
                        fma2(ar[r][0], xa0, w.a); fma2(ar[r][0], xb0, w.b);
                        fma2(ar[r][1], xa1, w.a); fma2(ar[r][1], xb1, w.b);
                        w = *(const U2*)&sm64[WXG + wi];
                        fma2(ag[r][0], xa0, w.a); fma2(ag[r][0], xb0, w.b);
                        fma2(ag[r][1], xa1, w.a); fma2(ag[r][1], xb1, w.b);
                        w = *(const U2*)&sm64[WHZ + wi];
                        fma2(az[r][0], ha0, w.a); fma2(az[r][0], hb0, w.b);
                        fma2(az[r][1], ha1, w.a); fma2(az[r][1], hb1, w.b);
                        w = *(const U2*)&sm64[WHR + wi];
                        fma2(ar[r][0], ha0, w.a); fma2(ar[r][0], hb0, w.b);
                        fma2(ar[r][1], ha1, w.a); fma2(ar[r][1], hb1, w.b);
                    }
                }
            }

            // ---- warp-local reduction over ks; publishers compute gates ----
#pragma unroll
            for (int r = 0; r < 2; r++)
#pragma unroll
                for (int j = 0; j < 2; j++) {
                    az[r][j] = red8(az[r][j]);
                    ar[r][j] = red8(ar[r][j]);
                    ag[r][j] = red8(ag[r][j]);
                }
            if (pub) {
                int bz = (l == 0 ? 0 : 3) * 16;
                int br = (l == 0 ? 1 : 4) * 16;
                int bgi = (l == 0 ? 2 : 5) * 16;
#pragma unroll
                for (int r = 0; r < 2; r++) {
                    float biz = smf[BIASF + bz + wr0 + r];
                    float bir = smf[BIASF + br + wr0 + r];
                    float big = smf[BIASF + bgi + wr0 + r];
#pragma unroll
                    for (int j = 0; j < 2; j++) {
                        float zvv = sigf(foldu(az[r][j]) + biz);
                        float rvv = sigf(foldu(ar[r][j]) + bir);
                        zv[r][j] = zvv;
                        sg[r][j] = foldu(ag[r][j]) + big;
                        __stcg(&g_rh[l][(b0a + j) * H_ + row_abs0 + r],
                               rvv * h_reg[l][r][j]);
                    }
                }
            }
            gbar(bg, target);

            // ============ phase B: (r*h) @ Whg^T =============================
            {
                u64 agg[2][2];
#pragma unroll
                for (int r = 0; r < 2; r++)
#pragma unroll
                    for (int j = 0; j < 2; j++) agg[r][j] = 0ull;
                const float4* rp0 = (const float4*)(g_rh[l] + b0a * H_);
                const float4* rp1 = rp0 + H_ / 4;
                float4 qr0[2], qr1[2];
#pragma unroll
                for (int i = 0; i < 2; i++) {
                    qr0[i] = __ldcg(rp0 + i * 8 + ks);
                    qr1[i] = __ldcg(rp1 + i * 8 + ks);
                }
#pragma unroll
                for (int kk = 0; kk < 16; kk++) {
                    u64 ra0, rb0, ra1, rb1;
                    pack2(qr0[kk & 1], ra0, rb0);
                    pack2(qr1[kk & 1], ra1, rb1);
                    if (kk < 14) {
                        int c = (kk + 2) * 8 + ks;
                        qr0[kk & 1] = __ldcg(rp0 + c);
                        qr1[kk & 1] = __ldcg(rp1 + c);
                    }
#pragma unroll
                    for (int r = 0; r < 2; r++) {
                        U2 w = *(const U2*)&sm64[WHG + (((wr0 + r) * 16 + kk) * 8 + ks) * 2];
                        fma2(agg[r][0], ra0, w.a); fma2(agg[r][0], rb0, w.b);
                        fma2(agg[r][1], ra1, w.a); fma2(agg[r][1], rb1, w.b);
                    }
                }
#pragma unroll
                for (int r = 0; r < 2; r++)
#pragma unroll
                    for (int j = 0; j < 2; j++) agg[r][j] = red8(agg[r][j]);
                if (pub) {
#pragma unroll
                    for (int r = 0; r < 2; r++)
#pragma unroll
                        for (int j = 0; j < 2; j++) {
                            float gv = tanhfast(sg[r][j] + foldu(agg[r][j]));
                            float hold = h_reg[l][r][j];
                            float hn = fmaf(zv[r][j], hold - gv, gv);
                            h_reg[l][r][j] = hn;
                            __stcg(&g_h[l][(b0a + j) * H_ + row_abs0 + r], hn);
                            if (l == 2)
                                g_hist[((size_t)t * H_ + row_abs0 + r) * B_ +
                                       (b0a + j)] = hn;
                        }
                }
            }
            // barrier needed after B for l=0,1 (next layer reads g_h[l]);
            // skipped after l=2 (per-layer g_rh buffers; g_h[2] next read is
            // 4 barriers away at t+1 l2-A).
            if (l < 2) gbar(bg, target);
        }
        gbar(bg, target);   // end-of-step: protects g_h[0] reuse at t+1 l0-A
    }
}

// ---------------- epilogue: out = hist @ Wout^T + bout ----------------------
__global__ void __launch_bounds__(256) out_proj_kernel(
    const float* __restrict__ Wout, const float* __restrict__ bout,
    float* __restrict__ out)
{
    extern __shared__ float sh[];   // 64 KB: hist[t] in [k][b]
    int t = blockIdx.x;
    int tid = threadIdx.x;
    const float* src = g_hist + (size_t)t * (H_ * B_);
    for (int j = tid; j < (H_ * B_) / 4; j += 256)
        ((float4*)sh)[j] = ((const float4*)src)[j];
    __syncthreads();

    int o0 = (tid >> 3) * 4;
    int b0 = (tid & 7) * 4;
    float acc[4][4];
#pragma unroll
    for (int i = 0; i < 4; i++)
#pragma unroll
        for (int j = 0; j < 4; j++) acc[i][j] = 0.f;

    for (int k = 0; k < H_; k += 4) {
        float4 h0 = *(const float4*)&sh[(k + 0) * 32 + b0];
        float4 h1 = *(const float4*)&sh[(k + 1) * 32 + b0];
        float4 h2 = *(const float4*)&sh[(k + 2) * 32 + b0];
        float4 h3 = *(const float4*)&sh[(k + 3) * 32 + b0];
#pragma unroll
        for (int i = 0; i < 4; i++) {
            float4 w = __ldg((const float4*)&Wout[(o0 + i) * H_ + k]);
            acc[i][0] = fmaf(w.x, h0.x, acc[i][0]);
            acc[i][0] = fmaf(w.y, h1.x, acc[i][0]);
            acc[i][0] = fmaf(w.z, h2.x, acc[i][0]);
            acc[i][0] = fmaf(w.w, h3.x, acc[i][0]);
            acc[i][1] = fmaf(w.x, h0.y, acc[i][1]);
            acc[i][1] = fmaf(w.y, h1.y, acc[i][1]);
            acc[i][1] = fmaf(w.z, h2.y, acc[i][1]);
            acc[i][1] = fmaf(w.w, h3.y, acc[i][1]);
            acc[i][2] = fmaf(w.x, h0.z, acc[i][2]);
            acc[i][2] = fmaf(w.y, h1.z, acc[i][2]);
            acc[i][2] = fmaf(w.z, h2.z, acc[i][2]);
            acc[i][2] = fmaf(w.w, h3.z, acc[i][2]);
            acc[i][3] = fmaf(w.x, h0.w, acc[i][3]);
            acc[i][3] = fmaf(w.y, h1.w, acc[i][3]);
            acc[i][3] = fmaf(w.z, h2.w, acc[i][3]);
            acc[i][3] = fmaf(w.w, h3.w, acc[i][3]);
        }
    }
#pragma unroll
    for (int j = 0; j < 4; j++)
#pragma unroll
        for (int i = 0; i < 4; i++)
            out[((size_t)(b0 + j) * S_ + t) * OUT_ + o0 + i] =
                acc[i][j] + __ldg(&bout[o0 + i]);
}

// ---------------- epilogue: final hidden state (B, L, H) --------------------
__global__ void final_state_kernel(float* __restrict__ out2) {
    int idx = blockIdx.x * blockDim.x + threadIdx.x;
    if (idx < 3 * B_ * H_) {
        int b = idx / (3 * H_);
        int rem = idx % (3 * H_);
        int l = rem >> 9;
        int k = rem & 511;
        out2[idx] = g_h[l][b * H_ + k];
    }
}

// ---------------- launch ----------------------------------------------------
extern "C" void kernel_launch(void* const* d_in, const int* in_sizes, int n_in,
                              void* d_out, int out_size) {
    const float* x    = (const float*)d_in[0];
    const float* h0   = (const float*)d_in[1];
    const float* W0z  = (const float*)d_in[2];
    const float* b0z  = (const float*)d_in[3];
    const float* W0r  = (const float*)d_in[4];
    const float* b0r  = (const float*)d_in[5];
    const float* W0g  = (const float*)d_in[6];
    const float* b0g  = (const float*)d_in[7];
    const float* Wxz  = (const float*)d_in[8];
    const float* bxz  = (const float*)d_in[9];
    const float* Wxr  = (const float*)d_in[10];
    const float* bxr  = (const float*)d_in[11];
    const float* Wxg  = (const float*)d_in[12];
    const float* bxg  = (const float*)d_in[13];
    const float* Whz  = (const float*)d_in[14];
    const float* Whr  = (const float*)d_in[15];
    const float* Whg  = (const float*)d_in[16];
    const float* Wout = (const float*)d_in[17];
    const float* bout = (const float*)d_in[18];
    float* out = (float*)d_out;

    cudaFuncSetAttribute(gru_persistent,
                         cudaFuncAttributeMaxDynamicSharedMemorySize, SMEM_BYTES);
    cudaFuncSetAttribute(out_proj_kernel,
                         cudaFuncAttributeMaxDynamicSharedMemorySize, 65536);

    init_kernel<<<192, 256>>>(h0);
    gru_persistent<<<NCTA, NTHR, SMEM_BYTES>>>(
        x, h0,
        W0z, b0z, W0r, b0r, W0g, b0g,
        Wxz, bxz, Wxr, bxr, Wxg, bxg,
        Whz, Whr, Whg);
    out_proj_kernel<<<S_, 256, 65536>>>(Wout, bout, out);
    final_state_kernel<<<192, 256>>>(out + (size_t)B_ * S_ * OUT_);
}

// round 17
// speedup vs baseline: 1.0394x; 1.0394x over previous
#include <cuda_runtime.h>

typedef unsigned long long u64;

#define NCTA 128
#define NTHR 256
#define B_   32
#define S_   1024
#define IN_  128
#define H_   512
#define OUT_ 128

// ---------------- device scratch (static __device__ arrays: allowed) --------
__device__ unsigned g_cnt[4][32];                               // per-group barrier
__device__ __align__(128) float g_h[3][B_ * H_];                // state [l][b][k]
__device__ __align__(128) float g_rh[3][B_ * H_];               // r*h  [l][b][k]
__device__ __align__(128) float g_xz[(size_t)S_ * H_ * B_];     // precomp [t][row][b]
__device__ __align__(128) float g_xr[(size_t)S_ * H_ * B_];
__device__ __align__(128) float g_xg[(size_t)S_ * H_ * B_];
__device__ __align__(128) float g_hist[(size_t)S_ * H_ * B_];   // [t][row][b]

// ---------------- SMEM layout ------------------------------------------------
// weights as k-pairs {w[k],w[k+1]}, layout [row16][kk16][ks8][q4] floats
// (U2 = LDS.128 per row/mat: 8 ks lanes x 16B = 128B unique, 4x bgrp broadcast)
#define WXZ 0
#define WXR 4096
#define WXG 8192
#define WHZ 12288
#define WHR 16384
#define WHG 20480
#define SM64_W 24576
#define FA (SM64_W * 2)             // float idx: staged slice A (x / r*h), [8][516]
#define FH (FA + 4128)              // staged slice B (h), [8][516]
#define FB (FH + 4128)              // biases bxz/bxr/bxg [3][16]
#define SMEM_BYTES ((FB + 48) * 4)  // 229,824 B  (<= 232,448 cap)

struct alignas(16) U2 { u64 a, b; };

__device__ __forceinline__ void fma2(u64& c, u64 a, u64 b) {
    asm("fma.rn.f32x2 %0, %1, %2, %0;" : "+l"(c) : "l"(a), "l"(b));
}
__device__ __forceinline__ void add2(u64& c, u64 a) {
    asm("add.rn.f32x2 %0, %0, %1;" : "+l"(c) : "l"(a));
}
__device__ __forceinline__ void pack2(const float4 v, u64& lo, u64& hi) {
    asm("mov.b64 %0, {%1, %2};" : "=l"(lo) : "f"(v.x), "f"(v.y));
    asm("mov.b64 %0, {%1, %2};" : "=l"(hi) : "f"(v.z), "f"(v.w));
}
__device__ __forceinline__ u64 dup2(float w) {
    u64 u;
    asm("mov.b64 %0, {%1, %1};" : "=l"(u) : "f"(w));
    return u;
}
__device__ __forceinline__ float foldu(u64 v) {
    float lo, hi;
    asm("mov.b64 {%0, %1}, %2;" : "=f"(lo), "=f"(hi) : "l"(v));
    return lo + hi;
}
// reduce over the 8 ks lanes (xor 1,2,4 stays inside each bgrp octet)
__device__ __forceinline__ u64 red8(u64 v) {
    add2(v, __shfl_xor_sync(0xffffffffu, v, 1));
    add2(v, __shfl_xor_sync(0xffffffffu, v, 2));
    add2(v, __shfl_xor_sync(0xffffffffu, v, 4));
    return v;
}
__device__ __forceinline__ float sigf(float x) {
    return __fdividef(1.f, 1.f + __expf(-x));
}
__device__ __forceinline__ float tanhfast(float x) {
    return fmaf(2.f, __fdividef(1.f, 1.f + __expf(-2.f * x)), -1.f);
}

// 32-CTA batch-group barrier: release-arrive + acquire-poll
__device__ __forceinline__ void gbar(int bg, unsigned& target) {
    __syncthreads();
    if (threadIdx.x == 0) {
        target += 32;
        unsigned* c = &g_cnt[bg][0];
        asm volatile("red.release.gpu.global.add.u32 [%0], 1;" :: "l"(c) : "memory");
        unsigned v;
        do {
            asm volatile("ld.acquire.gpu.global.u32 %0, [%1];"
                         : "=r"(v) : "l"(c) : "memory");
        } while (v < target);
    }
    __syncthreads();
}

// ---------------- init: reset barriers, fill g_h from h0 --------------------
__global__ void init_kernel(const float* __restrict__ h0) {
    int idx = blockIdx.x * blockDim.x + threadIdx.x;
    if (idx < 128) ((unsigned*)g_cnt)[idx] = 0;
    if (idx < 3 * B_ * H_) {
        int l = idx >> 14;
        int rem = idx & 16383;
        int b = rem >> 9, k = rem & 511;
        g_h[l][b * H_ + k] = h0[b * (3 * H_) + l * H_ + k];
    }
}

// ---------------- precompute layer-0 input projections ----------------------
// g_x{z,r,g}[t][row][b] = sum_i x[b][t][i]*W0.[row][i] + b0.[row]
__global__ void __launch_bounds__(256) xproj_kernel(
    const float* __restrict__ x,
    const float* __restrict__ W0z, const float* __restrict__ b0z,
    const float* __restrict__ W0r, const float* __restrict__ b0r,
    const float* __restrict__ W0g, const float* __restrict__ b0g)
{
    __shared__ float sxt[IN_ * 34];     // x[t] transposed: [i][b] (pad 34)
    int t = blockIdx.x, tid = threadIdx.x;
    for (int idx = tid; idx < B_ * IN_; idx += 256) {
        int b = idx >> 7, i = idx & 127;
        sxt[i * 34 + b] = x[((size_t)b * S_ + t) * IN_ + i];
    }
    __syncthreads();
    for (int rr = 0; rr < 2; rr++) {
        int row = tid + rr * 256;
        u64 accz[16], accr[16], accg[16];
#pragma unroll
        for (int p = 0; p < 16; p++) { accz[p] = 0; accr[p] = 0; accg[p] = 0; }
        const float* wzp = W0z + row * IN_;
        const float* wrp = W0r + row * IN_;
        const float* wgp = W0g + row * IN_;
        for (int i = 0; i < IN_; i++) {
            u64 wz2 = dup2(__ldg(wzp + i));
            u64 wr2 = dup2(__ldg(wrp + i));
            u64 wg2 = dup2(__ldg(wgp + i));
            const float* ai = sxt + i * 34;
#pragma unroll
            for (int p = 0; p < 16; p++) {
                u64 a = *(const u64*)&ai[p * 2];
                fma2(accz[p], a, wz2);
                fma2(accr[p], a, wr2);
                fma2(accg[p], a, wg2);
            }
        }
        u64 bz2 = dup2(__ldg(b0z + row));
        u64 br2 = dup2(__ldg(b0r + row));
        u64 bg2 = dup2(__ldg(b0g + row));
        size_t base = ((size_t)t * H_ + row) * B_;
#pragma unroll
        for (int p = 0; p < 16; p++) {
            add2(accz[p], bz2); add2(accr[p], br2); add2(accg[p], bg2);
            *(u64*)&g_xz[base + p * 2] = accz[p];
            *(u64*)&g_xr[base + p * 2] = accr[p];
            *(u64*)&g_xg[base + p * 2] = accg[p];
        }
    }
}

// ---------------- persistent GRU kernel --------------------------------------
__global__ void __launch_bounds__(NTHR, 1) gru_persistent(
    const float* __restrict__ h0,
    const float* __restrict__ Wxz, const float* __restrict__ bxz,
    const float* __restrict__ Wxr, const float* __restrict__ bxr,
    const float* __restrict__ Wxg, const float* __restrict__ bxg,
    const float* __restrict__ Whz, const float* __restrict__ Whr,
    const float* __restrict__ Whg)
{
    extern __shared__ u64 sm64[];
    float* smf = (float*)sm64;
    const int tid = threadIdx.x;
    const int rowgrid = blockIdx.x >> 2, bg = blockIdx.x & 3;
    const int row_base = rowgrid * 16, b_base = bg * 8;

    // ---- stage weight slices (k-pair permuted layout, no duplication) ----
    for (int e = tid; e < 16 * H_; e += NTHR) {
        int r = e >> 9, k = e & 511;
        int c = k >> 2, q = k & 3;
        int fidx = (((r * 16 + (c >> 3)) * 8) + (c & 7)) * 4 + q;
        int gi = (row_base + r) * H_ + k;
        smf[WXZ * 2 + fidx] = Wxz[gi];
        smf[WXR * 2 + fidx] = Wxr[gi];
        smf[WXG * 2 + fidx] = Wxg[gi];
        smf[WHZ * 2 + fidx] = Whz[gi];
        smf[WHR * 2 + fidx] = Whr[gi];
        smf[WHG * 2 + fidx] = Whg[gi];
    }
    if (tid < 16) {
        smf[FB + 0 * 16 + tid] = bxz[row_base + tid];
        smf[FB + 1 * 16 + tid] = bxr[row_base + tid];
        smf[FB + 2 * 16 + tid] = bxg[row_base + tid];
    }
    __syncthreads();

    const int wr0  = (tid >> 5) * 2;        // warp's row pair
    const int bgrp = (tid >> 3) & 3;
    const int bl0  = bgrp * 2;              // local batch pair base
    const int b0a  = b_base + bl0;          // absolute batch (j=0)
    const int ks   = tid & 7;
    const bool pub = (ks == 0);
    const int row_abs0 = row_base + wr0;
    const int bsl  = tid >> 5;              // staging batch row (0..7)
    const int ln   = tid & 31;

    float h_reg[3][2][2], zv[2][2], sg[2][2];
#pragma unroll
    for (int l = 0; l < 3; l++)
#pragma unroll
        for (int r = 0; r < 2; r++)
#pragma unroll
            for (int j = 0; j < 2; j++)
                h_reg[l][r][j] =
                    h0[(size_t)(b0a + j) * (3 * H_) + l * H_ + row_abs0 + r];

    const int aA0 = (bl0 + 0) * 516, aA1 = (bl0 + 1) * 516;
    unsigned target = 0;

    for (int t = 0; t < S_; t++) {
        for (int l = 0; l < 3; l++) {
            // ---- stage activation slices for phase A ----
            {
                const float4* hs = (const float4*)(g_h[l] + (b_base + bsl) * H_);
                float* dh = smf + FH + bsl * 516;
                if (l > 0) {
                    const float4* xs = (const float4*)(g_h[l - 1] + (b_base + bsl) * H_);
                    float* dx = smf + FA + bsl * 516;
#pragma unroll
                    for (int i = 0; i < 4; i++) {
                        int c = ln + i * 32;
                        float4 v = __ldcg(xs + c);
                        *(float4*)&dx[c * 4] = v;
                        float4 w = __ldcg(hs + c);
                        *(float4*)&dh[c * 4] = w;
                    }
                } else {
#pragma unroll
                    for (int i = 0; i < 4; i++) {
                        int c = ln + i * 32;
                        float4 w = __ldcg(hs + c);
                        *(float4*)&dh[c * 4] = w;
                    }
                }
            }
            __syncthreads();

            // ============ phase A ============================================
            u64 az[2][2], ar[2][2], ag[2][2];
#pragma unroll
            for (int r = 0; r < 2; r++)
#pragma unroll
                for (int j = 0; j < 2; j++) {
                    az[r][j] = 0ull; ar[r][j] = 0ull; ag[r][j] = 0ull;
                }
            const float* sax = smf + FA;
            const float* sah = smf + FH;

            if (l == 0) {
#pragma unroll
                for (int kk = 0; kk < 16; kk++) {
                    int c4 = (kk * 8 + ks) * 4;
                    float4 qh0 = *(const float4*)&sah[aA0 + c4];
                    float4 qh1 = *(const float4*)&sah[aA1 + c4];
                    u64 ha0, hb0, ha1, hb1;
                    pack2(qh0, ha0, hb0);
                    pack2(qh1, ha1, hb1);
#pragma unroll
                    for (int r = 0; r < 2; r++) {
                        int wi = (((wr0 + r) * 16 + kk) * 8 + ks) * 2;
                        U2 w;
                        w = *(const U2*)&sm64[WHZ + wi];
                        fma2(az[r][0], ha0, w.a); fma2(az[r][0], hb0, w.b);
                        fma2(az[r][1], ha1, w.a); fma2(az[r][1], hb1, w.b);
                        w = *(const U2*)&sm64[WHR + wi];
                        fma2(ar[r][0], ha0, w.a); fma2(ar[r][0], hb0, w.b);
                        fma2(ar[r][1], ha1, w.a); fma2(ar[r][1], hb1, w.b);
                    }
                }
            } else {
#pragma unroll
                for (int kk = 0; kk < 16; kk++) {
                    int c4 = (kk * 8 + ks) * 4;
                    float4 qx0 = *(const float4*)&sax[aA0 + c4];
                    float4 qx1 = *(const float4*)&sax[aA1 + c4];
                    float4 qh0 = *(const float4*)&sah[aA0 + c4];
                    float4 qh1 = *(const float4*)&sah[aA1 + c4];
                    u64 xa0, xb0, xa1, xb1, ha0, hb0, ha1, hb1;
                    pack2(qx0, xa0, xb0);
                    pack2(qx1, xa1, xb1);
                    pack2(qh0, ha0, hb0);
                    pack2(qh1, ha1, hb1);
#pragma unroll
                    for (int r = 0; r < 2; r++) {
                        int wi = (((wr0 + r) * 16 + kk) * 8 + ks) * 2;
                        U2 w;
                        w = *(const U2*)&sm64[WXZ + wi];
                        fma2(az[r][0], xa0, w.a); fma2(az[r][0], xb0, w.b);
                        fma2(az[r][1], xa1, w.a); fma2(az[r][1], xb1, w.b);
                        w = *(const U2*)&sm64[WXR + wi];
                        fma2(ar[r][0], xa0, w.a); fma2(ar[r][0], xb0, w.b);
                        fma2(ar[r][1], xa1, w.a); fma2(ar[r][1], xb1, w.b);
                        w = *(const U2*)&sm64[WXG + wi];
                        fma2(ag[r][0], xa0, w.a); fma2(ag[r][0], xb0, w.b);
                        fma2(ag[r][1], xa1, w.a); fma2(ag[r][1], xb1, w.b);
                        w = *(const U2*)&sm64[WHZ + wi];
                        fma2(az[r][0], ha0, w.a); fma2(az[r][0], hb0, w.b);
                        fma2(az[r][1], ha1, w.a); fma2(az[r][1], hb1, w.b);
                        w = *(const U2*)&sm64[WHR + wi];
                        fma2(ar[r][0], ha0, w.a); fma2(ar[r][0], hb0, w.b);
                        fma2(ar[r][1], ha1, w.a); fma2(ar[r][1], hb1, w.b);
                    }
                }
            }

            // ---- warp-local reduction; publishers compute z, r, push r*h ---
#pragma unroll
            for (int r = 0; r < 2; r++)
#pragma unroll
                for (int j = 0; j < 2; j++) {
                    az[r][j] = red8(az[r][j]);
                    ar[r][j] = red8(ar[r][j]);
                    if (l > 0) ag[r][j] = red8(ag[r][j]);
                }
            if (pub) {
                if (l == 0) {
#pragma unroll
                    for (int r = 0; r < 2; r++)
#pragma unroll
                        for (int j = 0; j < 2; j++) {
                            size_t o = ((size_t)t * H_ + row_abs0 + r) * B_ + b0a + j;
                            float zp = __ldcg(&g_xz[o]);
                            float rp = __ldcg(&g_xr[o]);
                            float gp = __ldcg(&g_xg[o]);
                            zv[r][j] = sigf(foldu(az[r][j]) + zp);
                            float rv = sigf(foldu(ar[r][j]) + rp);
                            sg[r][j] = gp;
                            __stcg(&g_rh[0][(b0a + j) * H_ + row_abs0 + r],
                                   rv * h_reg[0][r][j]);
                        }
                } else {
#pragma unroll
                    for (int r = 0; r < 2; r++) {
                        float biz = smf[FB + 0 * 16 + wr0 + r];
                        float bir = smf[FB + 1 * 16 + wr0 + r];
                        float big = smf[FB + 2 * 16 + wr0 + r];
#pragma unroll
                        for (int j = 0; j < 2; j++) {
                            zv[r][j] = sigf(foldu(az[r][j]) + biz);
                            float rv = sigf(foldu(ar[r][j]) + bir);
                            sg[r][j] = foldu(ag[r][j]) + big;
                            __stcg(&g_rh[l][(b0a + j) * H_ + row_abs0 + r],
                                   rv * h_reg[l][r][j]);
                        }
                    }
                }
            }
            gbar(bg, target);

            // ---- stage r*h slice ----
            {
                const float4* rs = (const float4*)(g_rh[l] + (b_base + bsl) * H_);
                float* dr = smf + FA + bsl * 516;
#pragma unroll
                for (int i = 0; i < 4; i++) {
                    int c = ln + i * 32;
                    float4 v = __ldcg(rs + c);
                    *(float4*)&dr[c * 4] = v;
                }
            }
            __syncthreads();

            // ============ phase B: (r*h) @ Whg^T =============================
            {
                u64 agg[2][2];
#pragma unroll
                for (int r = 0; r < 2; r++)
#pragma unroll
                    for (int j = 0; j < 2; j++) agg[r][j] = 0ull;
#pragma unroll
                for (int kk = 0; kk < 16; kk++) {
                    int c4 = (kk * 8 + ks) * 4;
                    float4 qr0 = *(const float4*)&sax[aA0 + c4];
                    float4 qr1 = *(const float4*)&sax[aA1 + c4];
                    u64 ra0, rb0, ra1, rb1;
                    pack2(qr0, ra0, rb0);
                    pack2(qr1, ra1, rb1);
#pragma unroll
                    for (int r = 0; r < 2; r++) {
                        U2 w = *(const U2*)&sm64[WHG +
                                (((wr0 + r) * 16 + kk) * 8 + ks) * 2];
                        fma2(agg[r][0], ra0, w.a); fma2(agg[r][0], rb0, w.b);
                        fma2(agg[r][1], ra1, w.a); fma2(agg[r][1], rb1, w.b);
                    }
                }
#pragma unroll
                for (int r = 0; r < 2; r++)
#pragma unroll
                    for (int j = 0; j < 2; j++) agg[r][j] = red8(agg[r][j]);
                if (pub) {
#pragma unroll
                    for (int r = 0; r < 2; r++)
#pragma unroll
                        for (int j = 0; j < 2; j++) {
                            float gv = tanhfast(sg[r][j] + foldu(agg[r][j]));
                            float hold = h_reg[l][r][j];
                            float hn = fmaf(zv[r][j], hold - gv, gv);
                            h_reg[l][r][j] = hn;
                            __stcg(&g_h[l][(b0a + j) * H_ + row_abs0 + r], hn);
                            if (l == 2)
                                g_hist[((size_t)t * H_ + row_abs0 + r) * B_ +
                                       (b0a + j)] = hn;
                        }
                }
            }
            // barrier after B only for l<2 (next layer reads g_h[l]);
            // after l=2 the next dependent read is >=4 barriers away.
            if (l < 2) gbar(bg, target);
        }
    }
}

// ---------------- epilogue: out = hist @ Wout^T + bout ----------------------
__global__ void __launch_bounds__(256) out_proj_kernel(
    const float* __restrict__ Wout, const float* __restrict__ bout,
    float* __restrict__ out)
{
    extern __shared__ float sh[];   // 64 KB: hist[t] in [k][b]
    int t = blockIdx.x;
    int tid = threadIdx.x;
    const float* src = g_hist + (size_t)t * (H_ * B_);
    for (int j = tid; j < (H_ * B_) / 4; j += 256)
        ((float4*)sh)[j] = ((const float4*)src)[j];
    __syncthreads();

    int o0 = (tid >> 3) * 4;
    int b0 = (tid & 7) * 4;
    float acc[4][4];
#pragma unroll
    for (int i = 0; i < 4; i++)
#pragma unroll
        for (int j = 0; j < 4; j++) acc[i][j] = 0.f;

    for (int k = 0; k < H_; k += 4) {
        float4 h0 = *(const float4*)&sh[(k + 0) * 32 + b0];
        float4 h1 = *(const float4*)&sh[(k + 1) * 32 + b0];
        float4 h2 = *(const float4*)&sh[(k + 2) * 32 + b0];
        float4 h3 = *(const float4*)&sh[(k + 3) * 32 + b0];
#pragma unroll
        for (int i = 0; i < 4; i++) {
            float4 w = __ldg((const float4*)&Wout[(o0 + i) * H_ + k]);
            acc[i][0] = fmaf(w.x, h0.x, acc[i][0]);
            acc[i][0] = fmaf(w.y, h1.x, acc[i][0]);
            acc[i][0] = fmaf(w.z, h2.x, acc[i][0]);
            acc[i][0] = fmaf(w.w, h3.x, acc[i][0]);
            acc[i][1] = fmaf(w.x, h0.y, acc[i][1]);
            acc[i][1] = fmaf(w.y, h1.y, acc[i][1]);
            acc[i][1] = fmaf(w.z, h2.y, acc[i][1]);
            acc[i][1] = fmaf(w.w, h3.y, acc[i][1]);
            acc[i][2] = fmaf(w.x, h0.z, acc[i][2]);
            acc[i][2] = fmaf(w.y, h1.z, acc[i][2]);
            acc[i][2] = fmaf(w.z, h2.z, acc[i][2]);
            acc[i][2] = fmaf(w.w, h3.z, acc[i][2]);
            acc[i][3] = fmaf(w.x, h0.w, acc[i][3]);
            acc[i][3] = fmaf(w.y, h1.w, acc[i][3]);
            acc[i][3] = fmaf(w.z, h2.w, acc[i][3]);
            acc[i][3] = fmaf(w.w, h3.w, acc[i][3]);
        }
    }
#pragma unroll
    for (int j = 0; j < 4; j++)
#pragma unroll
        for (int i = 0; i < 4; i++)
            out[((size_t)(b0 + j) * S_ + t) * OUT_ + o0 + i] =
                acc[i][j] + __ldg(&bout[o0 + i]);
}

// ---------------- epilogue: final hidden state (B, L, H) --------------------
__global__ void final_state_kernel(float* __restrict__ out2) {
    int idx = blockIdx.x * blockDim.x + threadIdx.x;
    if (idx < 3 * B_ * H_) {
        int b = idx / (3 * H_);
        int rem = idx % (3 * H_);
        int l = rem >> 9;
        int k = rem & 511;
        out2[idx] = g_h[l][b * H_ + k];
    }
}

// ---------------- launch ----------------------------------------------------
extern "C" void kernel_launch(void* const* d_in, const int* in_sizes, int n_in,
                              void* d_out, int out_size) {
    const float* x    = (const float*)d_in[0];
    const float* h0   = (const float*)d_in[1];
    const float* W0z  = (const float*)d_in[2];
    const float* b0z  = (const float*)d_in[3];
    const float* W0r  = (const float*)d_in[4];
    const float* b0r  = (const float*)d_in[5];
    const float* W0g  = (const float*)d_in[6];
    const float* b0g  = (const float*)d_in[7];
    const float* Wxz  = (const float*)d_in[8];
    const float* bxz  = (const float*)d_in[9];
    const float* Wxr  = (const float*)d_in[10];
    const float* bxr  = (const float*)d_in[11];
    const float* Wxg  = (const float*)d_in[12];
    const float* bxg  = (const float*)d_in[13];
    const float* Whz  = (const float*)d_in[14];
    const float* Whr  = (const float*)d_in[15];
    const float* Whg  = (const float*)d_in[16];
    const float* Wout = (const float*)d_in[17];
    const float* bout = (const float*)d_in[18];
    float* out = (float*)d_out;

    cudaFuncSetAttribute(gru_persistent,
                         cudaFuncAttributeMaxDynamicSharedMemorySize, SMEM_BYTES);
    cudaFuncSetAttribute(out_proj_kernel,
                         cudaFuncAttributeMaxDynamicSharedMemorySize, 65536);

    init_kernel<<<192, 256>>>(h0);
    xproj_kernel<<<S_, 256>>>(x, W0z, b0z, W0r, b0r, W0g, b0g);
    gru_persistent<<<NCTA, NTHR, SMEM_BYTES>>>(
        h0,
        Wxz, bxz, Wxr, bxr, Wxg, bxg,
        Whz, Whr, Whg);
    out_proj_kernel<<<S_, 256, 65536>>>(Wout, bout, out);
    final_state_kernel<<<192, 256>>>(out + (size_t)B_ * S_ * OUT_);
}